// round 8
// baseline (speedup 1.0000x reference)
#include <cuda_runtime.h>

#define NCAMS 6
#define CFEAT 64
#define HH 88
#define WW 160
#define HWSZ (HH*WW)
#define NVOX 200000
#define TILE 32
#define WSTR 68    // padded w_no row stride (16B-aligned rows)
#define SFSTR 68   // padded sf row stride (17 float4s, odd -> conflict-free LDS.128)

__global__ __launch_bounds__(256, 5) void vox_fusion_kernel(
    const float* __restrict__ feat,    // [6,64,88,160]
    const float* __restrict__ maskp,   // [6,1,88,160]
    const float* __restrict__ Kmat,    // [6,4,4]
    const float* __restrict__ extp,    // [6,4,4]
    const float* __restrict__ w_no,    // [64,65]
    const float* __restrict__ b_no,    // [64]
    const float* __restrict__ w_o,     // [64,130]
    const float* __restrict__ b_o,     // [64]
    float* __restrict__ out)           // [64, 200000]
{
    __shared__ float sE[NCAMS][12];
    __shared__ float sK[NCAMS][9];
    __shared__ unsigned svalid[NCAMS];
    __shared__ float4 scw[NCAMS * TILE];
    __shared__ int4   soff[NCAMS * TILE];
    __shared__ float  svz[NCAMS * TILE];
    __shared__ float  sf1[TILE * SFSTR];
    __shared__ float  sf2[TILE * SFSTR];
    __shared__ float  swno[CFEAT * WSTR];
    __shared__ float  sbno[CFEAT];

    const int t = threadIdx.x;
    const int i = t & 31;
    const int j = t >> 5;
    const int n = blockIdx.x * TILE + i;

    if (t < 72) {
        sE[t / 12][t % 12] = extp[(t / 12) * 16 + (t % 12)];
    } else if (t < 126) {
        int u = t - 72; int cam = u / 9, e = u % 9;
        sK[cam][e] = Kmat[cam * 16 + (e / 3) * 4 + (e % 3)];
    }
    __syncthreads();

    // ---- Phase 0: projection + validity, one thread per (voxel, cam) ----
    if (t < 192) {
        const int cam = t >> 5;
        const int ixv = n % 100;
        const int iyv = (n / 100) % 100;
        const int izv = n / 10000;
        const float px = -50.0f + (float)ixv;
        const float py = -50.0f + (float)iyv;
        const float pz = -15.0f + 1.5f * (float)izv;

        const float* E  = sE[cam];
        const float* Km = sK[cam];
        float vx = fmaf(E[0], px, fmaf(E[1], py, fmaf(E[2],  pz, E[3])));
        float vy = fmaf(E[4], px, fmaf(E[5], py, fmaf(E[6],  pz, E[7])));
        float vz = fmaf(E[8], px, fmaf(E[9], py, fmaf(E[10], pz, E[11])));
        float cx = fmaf(Km[0], vx, fmaf(Km[1], vy, Km[2] * vz));
        float cy = fmaf(Km[3], vx, fmaf(Km[4], vy, Km[5] * vz));
        float cz = fmaf(Km[6], vx, fmaf(Km[7], vy, Km[8] * vz));
        float denom = cz + 1e-8f;
        float pixx = cx / denom;
        float pixy = cy / denom;
        float gx = (pixx / 159.0f - 0.5f) * 2.0f;
        float gy = (pixy / 87.0f  - 0.5f) * 2.0f;
        bool oob = (gx > 1.0f) || (gx < -1.0f) || (gy > 1.0f) || (gy < -1.0f);
        float x = (gx + 1.0f) * 0.5f * 159.0f;
        float y = (gy + 1.0f) * 0.5f * 87.0f;
        float xr = rintf(x), yr = rintf(y);
        float mv = 0.0f;
        if (xr >= 0.0f && xr <= 159.0f && yr >= 0.0f && yr <= 87.0f)
            mv = __ldg(&maskp[cam * HWSZ + (int)yr * WW + (int)xr]);
        bool valid = (mv > 0.5f) && (vz > 0.0f) && (!oob);

        float4 cw4 = make_float4(0.f, 0.f, 0.f, 0.f);
        int4   o4  = make_int4(0, 0, 0, 0);
        float  vzc = 0.0f;
        if (valid) {
            float x0 = floorf(x), y0 = floorf(y);
            float wx1 = x - x0, wx0 = 1.0f - wx1;
            float wy1 = y - y0, wy0 = 1.0f - wy1;
            float xs2[2] = {x0, x0 + 1.0f}, wxa[2] = {wx0, wx1};
            float ys2[2] = {y0, y0 + 1.0f}, wya[2] = {wy0, wy1};
            float cw[4]; int off[4];
            int idx = 0;
#pragma unroll
            for (int a = 0; a < 2; a++) {
#pragma unroll
                for (int b = 0; b < 2; b++) {
                    float xi = xs2[a], yi = ys2[b];
                    bool v = (xi >= 0.0f) && (xi <= 159.0f) && (yi >= 0.0f) && (yi <= 87.0f);
                    float xc = fminf(fmaxf(xi, 0.0f), 159.0f);
                    float yc = fminf(fmaxf(yi, 0.0f), 87.0f);
                    off[idx] = (int)yc * WW + (int)xc;
                    cw[idx]  = wxa[a] * wya[b] * (v ? 1.0f : 0.0f);
                    idx++;
                }
            }
            cw4 = make_float4(cw[0], cw[1], cw[2], cw[3]);
            o4  = make_int4(off[0], off[1], off[2], off[3]);
            vzc = vz * 0.01f;
        }
        unsigned bal = __ballot_sync(0xffffffffu, valid);
        if (i == 0) svalid[cam] = bal;
        scw[t]  = cw4;
        soff[t] = o4;
        svz[t]  = vzc;
    }
    __syncthreads();

    const unsigned g1m = svalid[0] | svalid[3] | svalid[4];
    int cnt = 0;
#pragma unroll
    for (int c = 0; c < NCAMS; c++) cnt += (svalid[c] >> i) & 1;
    const unsigned m1 = __ballot_sync(0xffffffffu, cnt == 1);
    const unsigned m2 = __ballot_sync(0xffffffffu, cnt == 2);

    // ---- Fully-inactive tile: zero out and leave ----
    if ((m1 | m2) == 0u) {
#pragma unroll
        for (int m = 0; m < 8; m++)
            out[(j * 8 + m) * NVOX + n] = 0.0f;
        return;
    }

    // ---- Stage w_no only if some voxel has cnt==1 (overlaps phase 1) ----
    if (m1) {
        for (int idx = t; idx < CFEAT * 65; idx += 256) {
            int r = idx / 65, c = idx - r * 65;
            swno[r * WSTR + c] = w_no[idx];
        }
        if (t < CFEAT) sbno[t] = b_no[t];
    }

    // ---- Phase 1: gather for voxels with count 1 or 2 ----
    const bool active = (cnt == 1) || (cnt == 2);
    if (active) {
        float acc1[8], acc2[8];
#pragma unroll
        for (int k = 0; k < 8; k++) { acc1[k] = 0.0f; acc2[k] = 0.0f; }
#pragma unroll
        for (int cam = 0; cam < NCAMS; cam++) {
            if ((svalid[cam] >> i) & 1) {
                float4 w4 = scw[cam * TILE + i];
                int4   o4 = soff[cam * TILE + i];
                const float* base = feat + cam * (CFEAT * HWSZ) + (j * 8) * HWSZ;
                const bool g1 = (cam == 0) || (cam == 3) || (cam == 4);
#pragma unroll
                for (int k = 0; k < 8; k++) {
                    const float* bk = base + k * HWSZ;
                    float v0 = __ldg(bk + o4.x);
                    float v1 = __ldg(bk + o4.y);
                    float v2 = __ldg(bk + o4.z);
                    float v3 = __ldg(bk + o4.w);
                    float val = fmaf(v3, w4.w, fmaf(v2, w4.z, fmaf(v1, w4.y, v0 * w4.x)));
                    if (g1) acc1[k] += val; else acc2[k] += val;
                }
            }
        }
        // vectorized dumps: rows are 16B-aligned (SFSTR=68, j*8 multiple of 8)
        float* p1 = sf1 + i * SFSTR + j * 8;
        float* p2 = sf2 + i * SFSTR + j * 8;
        *(float4*)(p1 + 0) = make_float4(acc1[0], acc1[1], acc1[2], acc1[3]);
        *(float4*)(p1 + 4) = make_float4(acc1[4], acc1[5], acc1[6], acc1[7]);
        *(float4*)(p2 + 0) = make_float4(acc2[0], acc2[1], acc2[2], acc2[3]);
        *(float4*)(p2 + 4) = make_float4(acc2[4], acc2[5], acc2[6], acc2[7]);
        if (j == 0) {
            sf1[i * SFSTR + 64] = svz[0 * TILE + i] + svz[3 * TILE + i] + svz[4 * TILE + i];
            sf2[i * SFSTR + 64] = svz[1 * TILE + i] + svz[2 * TILE + i] + svz[5 * TILE + i];
        }
    }
    __syncthreads();

    // ---- Phase 2: per-voxel linear + ELU ----
    float s[8];
#pragma unroll
    for (int m = 0; m < 8; m++) s[m] = 0.0f;

    if (cnt == 1) {
        const bool useg1 = (g1m >> i) & 1;
        const float* fptr = (useg1 ? sf1 : sf2) + i * SFSTR;
#pragma unroll
        for (int m = 0; m < 8; m++) s[m] = sbno[j * 8 + m];
        const float* wrow = swno + (j * 8) * WSTR;
#pragma unroll 4
        for (int kt = 0; kt < 64; kt += 4) {
            float4 f = *(const float4*)(fptr + kt);     // conflict-free LDS.128
#pragma unroll
            for (int m = 0; m < 8; m++) {
                float4 w = *(const float4*)(wrow + m * WSTR + kt);  // broadcast LDS.128
                s[m] = fmaf(w.x, f.x, s[m]);
                s[m] = fmaf(w.y, f.y, s[m]);
                s[m] = fmaf(w.z, f.z, s[m]);
                s[m] = fmaf(w.w, f.w, s[m]);
            }
        }
        float f64 = fptr[64];
#pragma unroll
        for (int m = 0; m < 8; m++)
            s[m] = fmaf(wrow[m * WSTR + 64], f64, s[m]);
#pragma unroll
        for (int m = 0; m < 8; m++) s[m] = (s[m] > 0.0f) ? s[m] : expm1f(s[m]);
    } else if (cnt == 2) {
        const float* fp1 = sf1 + i * SFSTR;
        const float* fp2 = sf2 + i * SFSTR;
        const float* w = w_o + (j * 8) * 130;
#pragma unroll
        for (int m = 0; m < 8; m++) s[m] = __ldg(&b_o[j * 8 + m]);
        // group-1 half: rows start at 520m bytes (8B aligned) -> float2 pairs k=0..63
#pragma unroll 2
        for (int kt = 0; kt < 64; kt += 2) {
            float2 f = *(const float2*)(fp1 + kt);      // 8B-aligned (kt even)
#pragma unroll
            for (int m = 0; m < 8; m++) {
                float2 wv = __ldg((const float2*)(w + m * 130 + kt));
                s[m] = fmaf(wv.x, f.x, fmaf(wv.y, f.y, s[m]));
            }
        }
        {
            float f64 = fp1[64];
#pragma unroll
            for (int m = 0; m < 8; m++)
                s[m] = fmaf(__ldg(&w[m * 130 + 64]), f64, s[m]);
        }
        // group-2 half: +65 offset -> 8B-aligned at odd k; scalar k=0, pairs k=1..64
        {
            float f0 = fp2[0];
#pragma unroll
            for (int m = 0; m < 8; m++)
                s[m] = fmaf(__ldg(&w[m * 130 + 65]), f0, s[m]);
        }
#pragma unroll 2
        for (int kt = 1; kt < 65; kt += 2) {
            float fa = fp2[kt], fb = fp2[kt + 1];
#pragma unroll
            for (int m = 0; m < 8; m++) {
                float2 wv = __ldg((const float2*)(w + m * 130 + 65 + kt));
                s[m] = fmaf(wv.x, fa, fmaf(wv.y, fb, s[m]));
            }
        }
#pragma unroll
        for (int m = 0; m < 8; m++) s[m] = (s[m] > 0.0f) ? s[m] : expm1f(s[m]);
    }
#pragma unroll
    for (int m = 0; m < 8; m++)
        out[(j * 8 + m) * NVOX + n] = s[m];
}

extern "C" void kernel_launch(void* const* d_in, const int* in_sizes, int n_in,
                              void* d_out, int out_size) {
    const float* feat  = (const float*)d_in[0];
    const float* maskp = (const float*)d_in[1];
    const float* Kmat  = (const float*)d_in[2];
    const float* extp  = (const float*)d_in[3];
    const float* w_no  = (const float*)d_in[4];
    const float* b_no  = (const float*)d_in[5];
    const float* w_o   = (const float*)d_in[6];
    const float* b_o   = (const float*)d_in[7];
    float* out = (float*)d_out;
    vox_fusion_kernel<<<NVOX / TILE, 256>>>(feat, maskp, Kmat, extp,
                                            w_no, b_no, w_o, b_o, out);
}